// round 13
// baseline (speedup 1.0000x reference)
#include <cuda_runtime.h>

#define NSTATES 128

#define FMA2(acc, p, t) \
    asm volatile("fma.rn.f32x2 %0, %1, %2, %0;" : "+l"(acc) : "l"(p), "l"(t))
#define ADD2(acc, b) \
    asm volatile("add.rn.f32x2 %0, %0, %1;" : "+l"(acc) : "l"(b))
#define LDSV2O(x, y, base, OFF) \
    asm volatile("ld.shared.v2.u64 {%0,%1}, [%2+%3];" \
                 : "=l"(x), "=l"(y) : "r"(base), "n"(OFF))

static __device__ __forceinline__ float warp_max(float v) {
#pragma unroll
    for (int d = 16; d; d >>= 1) v = fmaxf(v, __shfl_xor_sync(0xffffffffu, v, d));
    return v;
}
static __device__ __forceinline__ float warp_sum(float v) {
#pragma unroll
    for (int d = 16; d; d >>= 1) v += __shfl_xor_sync(0xffffffffu, v, d);
    return v;
}

// One fused scan step advancing TWO independent batches (A, B) sharing tc.
// q[j] = sum_i p[i]*T[i][j] for each batch; p'[j] = q[j]*eo.
// MODE 0: plain. MODE 1: also block-max of new p (both batches) into wredA/B.
// MODE 2: apply renorm from previous MODE-1 maxes, accumulate log into CA/CB.
template <int MODE>
static __device__ __forceinline__ void crf_step2(
    const unsigned long long (&tc)[64],
    unsigned int pa, unsigned int pb,          // SMEM addrs of input p (A, B)
    float* __restrict__ outA, float* __restrict__ outB,
    float eoA, float eoB,
    float& CA, float& CB,
    float* wredA, float* wredB,
    int warp, int lane, int j,
    float& pnA_o, float& pnB_o)
{
    unsigned long long vA[8], vB[8];
    unsigned long long aA[4] = {0ull, 0ull, 0ull, 0ull};
    unsigned long long aB[4] = {0ull, 0ull, 0ull, 0ull};

    LDSV2O(vA[0], vA[1], pa, 0);
    LDSV2O(vB[0], vB[1], pb, 0);
    LDSV2O(vA[2], vA[3], pa, 16);
    LDSV2O(vB[2], vB[3], pb, 16);
    LDSV2O(vA[4], vA[5], pa, 32);
    LDSV2O(vB[4], vB[5], pb, 32);
    LDSV2O(vA[6], vA[7], pa, 48);
    LDSV2O(vB[6], vB[7], pb, 48);

#define KS(k, PRE) do {                                                     \
    FMA2(aA[((k) & 1) * 2],     vA[((k) % 4) * 2],     tc[2 * (k)]);        \
    FMA2(aB[((k) & 1) * 2],     vB[((k) % 4) * 2],     tc[2 * (k)]);        \
    FMA2(aA[((k) & 1) * 2 + 1], vA[((k) % 4) * 2 + 1], tc[2 * (k) + 1]);    \
    FMA2(aB[((k) & 1) * 2 + 1], vB[((k) % 4) * 2 + 1], tc[2 * (k) + 1]);    \
    if (PRE) {                                                              \
        LDSV2O(vA[((k) % 4) * 2], vA[((k) % 4) * 2 + 1], pa, ((k) + 4) * 16); \
        LDSV2O(vB[((k) % 4) * 2], vB[((k) % 4) * 2 + 1], pb, ((k) + 4) * 16); \
    } } while (0)

    KS(0, 1);  KS(1, 1);  KS(2, 1);  KS(3, 1);
    KS(4, 1);  KS(5, 1);  KS(6, 1);  KS(7, 1);
    KS(8, 1);  KS(9, 1);  KS(10, 1); KS(11, 1);
    KS(12, 1); KS(13, 1); KS(14, 1); KS(15, 1);
    KS(16, 1); KS(17, 1); KS(18, 1); KS(19, 1);
    KS(20, 1); KS(21, 1); KS(22, 1); KS(23, 1);
    KS(24, 1); KS(25, 1); KS(26, 1); KS(27, 1);
    KS(28, 0); KS(29, 0); KS(30, 0); KS(31, 0);
#undef KS

    ADD2(aA[0], aA[2]); ADD2(aB[0], aB[2]);
    ADD2(aA[1], aA[3]); ADD2(aB[1], aB[3]);
    ADD2(aA[0], aA[1]); ADD2(aB[0], aB[1]);
    float qAx, qAy, qBx, qBy;
    asm("mov.b64 {%0, %1}, %2;" : "=f"(qAx), "=f"(qAy) : "l"(aA[0]));
    asm("mov.b64 {%0, %1}, %2;" : "=f"(qBx), "=f"(qBy) : "l"(aB[0]));
    float qA = qAx + qAy;
    float qB = qBx + qBy;

    if (MODE == 2) {
        float4 wa = *reinterpret_cast<const float4*>(wredA);
        float4 wb = *reinterpret_cast<const float4*>(wredB);
        float mA = fmaxf(fmaxf(wa.x, wa.y), fmaxf(wa.z, wa.w));
        float mB = fmaxf(fmaxf(wb.x, wb.y), fmaxf(wb.z, wb.w));
        qA = qA * __fdividef(1.0f, mA);  CA += __logf(mA);
        qB = qB * __fdividef(1.0f, mB);  CB += __logf(mB);
    }

    float pnA = qA * eoA;
    float pnB = qB * eoB;
    outA[j] = pnA;
    outB[j] = pnB;

    if (MODE == 1) {
        float mA = warp_max(pnA);
        float mB = warp_max(pnB);
        if (lane == 0) { wredA[warp] = mA; wredB[warp] = mB; }
    }
    __syncthreads();
    pnA_o = pnA;
    pnB_o = pnB;
}

__global__ void __launch_bounds__(128, 1)
crf_forward_kernel(const float* __restrict__ obs,
                   const float* __restrict__ logA,
                   float* __restrict__ out, int T, int B)
{
    const int bA   = 2 * blockIdx.x;
    const int bBr  = 2 * blockIdx.x + 1;
    const int bB   = (bBr < B) ? bBr : bA;   // duplicate A if odd tail
    const int j    = threadIdx.x;
    const int warp = j >> 5;
    const int lane = j & 31;

    __shared__ __align__(16) float pshA[2][NSTATES];
    __shared__ __align__(16) float pshB[2][NSTATES];
    __shared__ __align__(16) float wredA[4];
    __shared__ __align__(16) float wredB[4];

    // Column j of exp(A): shared by both batches. 128 regs.
    unsigned long long tc[64];
#pragma unroll
    for (int m = 0; m < 64; ++m) {
        float2 t2;
        t2.x = expf(logA[(2 * m + 0) * NSTATES + j]);
        t2.y = expf(logA[(2 * m + 1) * NSTATES + j]);
        tc[m] = *reinterpret_cast<unsigned long long*>(&t2);
    }

    const unsigned int pA0 = (unsigned int)__cvta_generic_to_shared(pshA[0]);
    const unsigned int pA1 = (unsigned int)__cvta_generic_to_shared(pshA[1]);
    const unsigned int pB0 = (unsigned int)__cvta_generic_to_shared(pshB[0]);
    const unsigned int pB1 = (unsigned int)__cvta_generic_to_shared(pshB[1]);

    const float* objA = obs + (size_t)bA * ((size_t)T * NSTATES) + j;
    const float* objB = obs + (size_t)bB * ((size_t)T * NSTATES) + j;

    // ---- t = 0 init for both batches ----
    float o0A = objA[0];
    float o0B = objB[0];
    float mA0 = warp_max(o0A);
    float mB0 = warp_max(o0B);
    if (lane == 0) { wredA[warp] = mA0; wredB[warp] = mB0; }
    __syncthreads();
    mA0 = fmaxf(fmaxf(wredA[0], wredA[1]), fmaxf(wredA[2], wredA[3]));
    mB0 = fmaxf(fmaxf(wredB[0], wredB[1]), fmaxf(wredB[2], wredB[3]));
    float CA = mA0, CB = mB0;
    pshA[0][j] = __expf(o0A - mA0);
    pshB[0][j] = __expf(o0B - mB0);
    __syncthreads();

    // ---- prefetch ring: obs for t = 1..4 (both batches) ----
    float fA0 = objA[1 * NSTATES], fB0 = objB[1 * NSTATES];
    float fA1 = objA[2 * NSTATES], fB1 = objB[2 * NSTATES];
    float fA2 = objA[3 * NSTATES], fB2 = objB[3 * NSTATES];
    float fA3 = objA[4 * NSTATES], fB3 = objB[4 * NSTATES];

    const int offmax = (T - 1) * NSTATES;
    int off = 5 * NSTATES;

    const int G   = (T - 1) >> 3;   // groups of 8 fused steps (renorm per group)
    const int rem = (T - 1) & 7;    // T=4096 -> 7
    float pnA = 0.0f, pnB = 0.0f;

#define PF(fa, fb) do { int o_ = (off < offmax) ? off : offmax; \
                        fa = __ldg(objA + o_); fb = __ldg(objB + o_); \
                        off += NSTATES; } while (0)
#define ST2(MODE, IN, OUT, oa, ob)                                        \
    crf_step2<MODE>(tc, pA##IN, pB##IN, pshA[OUT], pshB[OUT],             \
                    __expf(oa), __expf(ob), CA, CB, wredA, wredB,         \
                    warp, lane, j, pnA, pnB)

    for (int g = 0; g < G; ++g) {
        float oa, ob;
        oa = fA0; ob = fB0; PF(fA0, fB0); ST2(0, 0, 1, oa, ob);
        oa = fA1; ob = fB1; PF(fA1, fB1); ST2(0, 1, 0, oa, ob);
        oa = fA2; ob = fB2; PF(fA2, fB2); ST2(0, 0, 1, oa, ob);
        oa = fA3; ob = fB3; PF(fA3, fB3); ST2(0, 1, 0, oa, ob);
        oa = fA0; ob = fB0; PF(fA0, fB0); ST2(0, 0, 1, oa, ob);
        oa = fA1; ob = fB1; PF(fA1, fB1); ST2(0, 1, 0, oa, ob);
        oa = fA2; ob = fB2; PF(fA2, fB2); ST2(1, 0, 1, oa, ob);
        oa = fA3; ob = fB3; PF(fA3, fB3); ST2(2, 1, 0, oa, ob);
    }

    // ---- tail (rem <= 7 plain steps; drift bounded, fp32-safe) ----
    {
        float oa, ob;
        if (rem > 0) { oa = fA0; ob = fB0; PF(fA0, fB0); ST2(0, 0, 1, oa, ob); }
        if (rem > 1) { oa = fA1; ob = fB1; PF(fA1, fB1); ST2(0, 1, 0, oa, ob); }
        if (rem > 2) { oa = fA2; ob = fB2; PF(fA2, fB2); ST2(0, 0, 1, oa, ob); }
        if (rem > 3) { oa = fA3; ob = fB3;               ST2(0, 1, 0, oa, ob); }
        if (rem > 4) { oa = fA0; ob = fB0;               ST2(0, 0, 1, oa, ob); }
        if (rem > 5) { oa = fA1; ob = fB1;               ST2(0, 1, 0, oa, ob); }
        if (rem > 6) { oa = fA2; ob = fB2;               ST2(0, 0, 1, oa, ob); }
    }
#undef PF
#undef ST2

    // ---- final: out[b] = -(C + log(sum_j p[j])) for both batches ----
    float sA = warp_sum(pnA);
    float sB = warp_sum(pnB);
    if (lane == 0) { wredA[warp] = sA; wredB[warp] = sB; }
    __syncthreads();
    if (j == 0) {
        float totA = (wredA[0] + wredA[1]) + (wredA[2] + wredA[3]);
        out[bA] = -(CA + logf(totA));
        if (bBr < B) {
            float totB = (wredB[0] + wredB[1]) + (wredB[2] + wredB[3]);
            out[bBr] = -(CB + logf(totB));
        }
    }
}

extern "C" void kernel_launch(void* const* d_in, const int* in_sizes, int n_in,
                              void* d_out, int out_size)
{
    const float* obs  = (const float*)d_in[0];   // [B, T, S] fp32
    const float* logA = (const float*)d_in[1];   // [S, S] fp32
    float* out = (float*)d_out;                  // [B] fp32

    const int B = out_size;                      // 64
    const int T = in_sizes[0] / (B * NSTATES);   // 4096

    crf_forward_kernel<<<(B + 1) / 2, NSTATES>>>(obs, logA, out, T, B);
}

// round 14
// speedup vs baseline: 1.3758x; 1.3758x over previous
#include <cuda_runtime.h>

#define NSTATES 128

#define FMA2(acc, p, t) \
    asm volatile("fma.rn.f32x2 %0, %1, %2, %0;" : "+l"(acc) : "l"(p), "l"(t))
#define ADD2(acc, b) \
    asm volatile("add.rn.f32x2 %0, %0, %1;" : "+l"(acc) : "l"(b))
#define BARG(id) \
    asm volatile("bar.sync %0, 128;" :: "r"(id) : "memory")

static __device__ __forceinline__ float warp_max(float v) {
#pragma unroll
    for (int d = 16; d; d >>= 1) v = fmaxf(v, __shfl_xor_sync(0xffffffffu, v, d));
    return v;
}
static __device__ __forceinline__ float warp_sum(float v) {
#pragma unroll
    for (int d = 16; d; d >>= 1) v += __shfl_xor_sync(0xffffffffu, v, d);
    return v;
}

// One scan step for ONE batch group (128 threads synchronized by named barrier
// `barid`): q[j] = sum_i p[i]*T[i][j];  p'[j] = q[j]*exp(obs[t,j]).
// MODE 0: plain. MODE 1: also block-max of p' into wred (for renorm).
// MODE 2: apply renorm from previous MODE-1 max, accumulate log into C.
template <int MODE>
static __device__ __forceinline__ float crf_step(
    const unsigned long long (&tc)[64],
    const float* __restrict__ pin, float* __restrict__ pout,
    float obsv, float& C, float* wred,
    int warp4, int lane, int j, int barid)
{
    float eo = __expf(obsv);

    unsigned long long a0 = 0ull, a1 = 0ull, a2 = 0ull, a3 = 0ull;
    const ulonglong2* pv = reinterpret_cast<const ulonglong2*>(pin);
#pragma unroll
    for (int k = 0; k < 32; k += 2) {
        ulonglong2 pa = pv[k];      // p[4k .. 4k+3]   (broadcast LDS.128)
        ulonglong2 pb = pv[k + 1];  // p[4k+4 .. 4k+7]
        FMA2(a0, pa.x, tc[2 * k + 0]);
        FMA2(a1, pa.y, tc[2 * k + 1]);
        FMA2(a2, pb.x, tc[2 * k + 2]);
        FMA2(a3, pb.y, tc[2 * k + 3]);
    }
    ADD2(a0, a2);
    ADD2(a1, a3);
    ADD2(a0, a1);
    float qx, qy;
    asm("mov.b64 {%0, %1}, %2;" : "=f"(qx), "=f"(qy) : "l"(a0));
    float q = qx + qy;

    if (MODE == 2) {
        float4 w = *reinterpret_cast<const float4*>(wred);
        float mx = fmaxf(fmaxf(w.x, w.y), fmaxf(w.z, w.w));
        q = q * __fdividef(1.0f, mx);
        C += __logf(mx);
    }

    float pn = q * eo;
    pout[j] = pn;

    if (MODE == 1) {
        float m = warp_max(pn);
        if (lane == 0) wred[warp4] = m;
    }
    BARG(barid);
    return pn;
}

__global__ void __launch_bounds__(256, 1)
crf_forward_kernel(const float* __restrict__ obs,
                   const float* __restrict__ logA,
                   float* __restrict__ out, int T, int B)
{
    const int t     = threadIdx.x;
    const int g     = t >> 7;            // 0: batch A (warps 0-3), 1: batch B (warps 4-7)
    const int j     = t & 127;           // state index within the group
    const int warp4 = j >> 5;            // warp index within the group
    const int lane  = t & 31;
    const int barid = g + 1;             // named barrier per group

    const int b = 2 * blockIdx.x + g;    // this group's batch
    const int bc = (b < B) ? b : (b - 1);

    __shared__ __align__(16) float psh[2][2][NSTATES];   // [group][pingpong][state]
    __shared__ __align__(16) float wred[2][4];

    float* wr = wred[g];

    // Column j of exp(A) in registers, packed as (i even, i odd) f32x2 pairs.
    // Identical per-thread footprint to the 1094us kernel: no extra live state.
    unsigned long long tc[64];
#pragma unroll
    for (int m = 0; m < 64; ++m) {
        float2 t2;
        t2.x = expf(logA[(2 * m + 0) * NSTATES + j]);
        t2.y = expf(logA[(2 * m + 1) * NSTATES + j]);
        tc[m] = *reinterpret_cast<unsigned long long*>(&t2);
    }

    const float* obj = obs + (size_t)bc * ((size_t)T * NSTATES) + j;

    // ---- t = 0: fv0 = obs[:,0,:], p = exp(fv0 - m0), C = m0 ----
    float o0 = obj[0];
    float m0 = warp_max(o0);
    if (lane == 0) wr[warp4] = m0;
    BARG(barid);
    m0 = fmaxf(fmaxf(wr[0], wr[1]), fmaxf(wr[2], wr[3]));
    float C = m0;
    psh[g][0][j] = __expf(o0 - m0);
    BARG(barid);

    // ---- prefetch ring: obs for t = 1..4 ----
    float f0 = obj[1 * NSTATES];
    float f1 = obj[2 * NSTATES];
    float f2 = obj[3 * NSTATES];
    float f3 = obj[4 * NSTATES];

    const int offmax = (T - 1) * NSTATES;
    int off = 5 * NSTATES;

    const int G   = (T - 1) >> 3;   // groups of 8 steps (renorm once per group)
    const int rem = (T - 1) & 7;    // T=4096 -> 7
    float pn = 0.0f;

#define PF(fr) do { fr = __ldg(obj + (off < offmax ? off : offmax)); off += NSTATES; } while (0)
#define ST(MODE, IN, OUT, o) \
    pn = crf_step<MODE>(tc, psh[g][IN], psh[g][OUT], o, C, wr, warp4, lane, j, barid)

    for (int gg = 0; gg < G; ++gg) {
        float o;
        o = f0; PF(f0); ST(0, 0, 1, o);
        o = f1; PF(f1); ST(0, 1, 0, o);
        o = f2; PF(f2); ST(0, 0, 1, o);
        o = f3; PF(f3); ST(0, 1, 0, o);
        o = f0; PF(f0); ST(0, 0, 1, o);
        o = f1; PF(f1); ST(0, 1, 0, o);
        o = f2; PF(f2); ST(1, 0, 1, o);
        o = f3; PF(f3); ST(2, 1, 0, o);
    }

    // ---- tail (rem <= 7 plain steps; drift bounded, fp32-safe) ----
    {
        float o;
        if (rem > 0) { o = f0; PF(f0); ST(0, 0, 1, o); }
        if (rem > 1) { o = f1; PF(f1); ST(0, 1, 0, o); }
        if (rem > 2) { o = f2; PF(f2); ST(0, 0, 1, o); }
        if (rem > 3) { o = f3;         ST(0, 1, 0, o); }
        if (rem > 4) { o = f0;         ST(0, 0, 1, o); }
        if (rem > 5) { o = f1;         ST(0, 1, 0, o); }
        if (rem > 6) { o = f2;         ST(0, 0, 1, o); }
    }
#undef PF
#undef ST

    // ---- final: out[b] = -(C + log(sum_j p[j])) ----
    float s = warp_sum(pn);
    if (lane == 0) wr[warp4] = s;
    BARG(barid);
    if (j == 0 && b < B) {
        float tot = (wr[0] + wr[1]) + (wr[2] + wr[3]);
        out[b] = -(C + logf(tot));
    }
}

extern "C" void kernel_launch(void* const* d_in, const int* in_sizes, int n_in,
                              void* d_out, int out_size)
{
    const float* obs  = (const float*)d_in[0];   // [B, T, S] fp32
    const float* logA = (const float*)d_in[1];   // [S, S] fp32
    float* out = (float*)d_out;                  // [B] fp32

    const int B = out_size;                      // 64
    const int T = in_sizes[0] / (B * NSTATES);   // 4096

    crf_forward_kernel<<<(B + 1) / 2, 256>>>(obs, logA, out, T, B);
}

// round 15
// speedup vs baseline: 3.4450x; 2.5039x over previous
#include <cuda_runtime.h>

#define NSTATES 128
#define MAXB    256

// Inter-kernel scratch (allocation-free: __device__ globals).
__device__ float g_u[MAXB * NSTATES];    // forward:  u = T^T alpha_mid
__device__ float g_d[MAXB * NSTATES];    // backward: delta_{mid+1}
__device__ float g_Cf[MAXB];
__device__ float g_Cb[MAXB];

#define FMA2(acc, p, t) \
    asm volatile("fma.rn.f32x2 %0, %1, %2, %0;" : "+l"(acc) : "l"(p), "l"(t))
#define ADD2(acc, b) \
    asm volatile("add.rn.f32x2 %0, %0, %1;" : "+l"(acc) : "l"(b))

static __device__ __forceinline__ float warp_max(float v) {
#pragma unroll
    for (int d = 16; d; d >>= 1) v = fmaxf(v, __shfl_xor_sync(0xffffffffu, v, d));
    return v;
}
static __device__ __forceinline__ float warp_sum(float v) {
#pragma unroll
    for (int d = 16; d; d >>= 1) v += __shfl_xor_sync(0xffffffffu, v, d);
    return v;
}

// One scan step: q[j] = sum_i p[i]*tc[i];  p'[j] = q[j]*exp(obsv).
// (tc = column j of T for forward, row j of T for backward.)
// MODE 0: plain. MODE 1: also block-max of p' into wred. MODE 2: apply renorm.
template <int MODE>
static __device__ __forceinline__ float crf_step(
    const unsigned long long (&tc)[64],
    const float* __restrict__ pin, float* __restrict__ pout,
    float obsv, float& C, float* wred, int warp, int lane, int j)
{
    float eo = __expf(obsv);

    unsigned long long a0 = 0ull, a1 = 0ull, a2 = 0ull, a3 = 0ull;
    const ulonglong2* pv = reinterpret_cast<const ulonglong2*>(pin);
#pragma unroll
    for (int k = 0; k < 32; k += 2) {
        ulonglong2 pa = pv[k];      // p[4k .. 4k+3]   (broadcast LDS.128)
        ulonglong2 pb = pv[k + 1];  // p[4k+4 .. 4k+7]
        FMA2(a0, pa.x, tc[2 * k + 0]);
        FMA2(a1, pa.y, tc[2 * k + 1]);
        FMA2(a2, pb.x, tc[2 * k + 2]);
        FMA2(a3, pb.y, tc[2 * k + 3]);
    }
    ADD2(a0, a2);
    ADD2(a1, a3);
    ADD2(a0, a1);
    float qx, qy;
    asm("mov.b64 {%0, %1}, %2;" : "=f"(qx), "=f"(qy) : "l"(a0));
    float q = qx + qy;

    if (MODE == 2) {
        float4 w = *reinterpret_cast<const float4*>(wred);
        float mx = fmaxf(fmaxf(w.x, w.y), fmaxf(w.z, w.w));
        q = q * __fdividef(1.0f, mx);
        C += __logf(mx);
    }

    float pn = q * eo;
    pout[j] = pn;

    if (MODE == 1) {
        float m = warp_max(pn);
        if (lane == 0) wred[warp] = m;
    }
    __syncthreads();
    return pn;
}

// Half-scan kernel: CTA 2b runs the forward half of batch b, CTA 2b+1 the
// backward half. Forward: alpha over obs rows 0..mid, then one extra plain
// matvec u = T^T alpha_mid. Backward: delta_t = eobs_t (.) (T delta_{t+1}),
// delta_{T-1} = eobs_{T-1}, down to t = mid+1.
__global__ void __launch_bounds__(128, 1)
crf_half_kernel(const float* __restrict__ obs,
                const float* __restrict__ logA,
                int T)
{
    const int cta  = blockIdx.x;
    const int b    = cta >> 1;
    const int dir  = cta & 1;            // 0 = forward, 1 = backward
    const int j    = threadIdx.x;
    const int warp = j >> 5;
    const int lane = j & 31;

    __shared__ __align__(16) float psh[2][NSTATES];
    __shared__ __align__(16) float wred[4];

    // Register copy of exp(logA): column j (fwd) or row j (bwd), f32x2 pairs.
    unsigned long long tc[64];
#pragma unroll
    for (int m = 0; m < 64; ++m) {
        float2 t2;
        if (dir == 0) {
            t2.x = expf(logA[(2 * m + 0) * NSTATES + j]);
            t2.y = expf(logA[(2 * m + 1) * NSTATES + j]);
        } else {
            t2.x = expf(logA[j * NSTATES + 2 * m + 0]);
            t2.y = expf(logA[j * NSTATES + 2 * m + 1]);
        }
        tc[m] = *reinterpret_cast<unsigned long long*>(&t2);
    }

    const int mid    = T >> 1;
    const int row0   = dir ? (T - 1) : 0;
    const int nsteps = dir ? (T - 2 - mid) : mid;
    const int dS     = dir ? -NSTATES : NSTATES;
    const int hi     = (T - 1) * NSTATES;

    const float* obj = obs + (size_t)b * ((size_t)T * NSTATES) + j;

    // ---- init: p = exp(obs[row0] - m0), C = m0 ----
    float o0 = obj[row0 * NSTATES];
    float m0 = warp_max(o0);
    if (lane == 0) wred[warp] = m0;
    __syncthreads();
    m0 = fmaxf(fmaxf(wred[0], wred[1]), fmaxf(wred[2], wred[3]));
    float C = m0;
    psh[0][j] = __expf(o0 - m0);
    __syncthreads();

    // ---- prefetch ring: next 4 obs rows in scan order ----
    float f0 = obj[row0 * NSTATES + 1 * dS];
    float f1 = obj[row0 * NSTATES + 2 * dS];
    float f2 = obj[row0 * NSTATES + 3 * dS];
    float f3 = obj[row0 * NSTATES + 4 * dS];
    int off = row0 * NSTATES + 5 * dS;

    const int G   = nsteps >> 3;   // groups of 8 steps (renorm once per group)
    const int rem = nsteps & 7;
    float pn = psh[0][j];

#define PF(fr) do { int oc = off; oc = (oc < 0) ? 0 : oc; oc = (oc > hi) ? hi : oc; \
                    fr = __ldg(obj + oc); off += dS; } while (0)
#define ST(MODE, IN, OUT, o) \
    pn = crf_step<MODE>(tc, psh[IN], psh[OUT], o, C, wred, warp, lane, j)

    for (int g = 0; g < G; ++g) {
        float o;
        o = f0; PF(f0); ST(0, 0, 1, o);
        o = f1; PF(f1); ST(0, 1, 0, o);
        o = f2; PF(f2); ST(0, 0, 1, o);
        o = f3; PF(f3); ST(0, 1, 0, o);
        o = f0; PF(f0); ST(0, 0, 1, o);
        o = f1; PF(f1); ST(0, 1, 0, o);
        o = f2; PF(f2); ST(1, 0, 1, o);
        o = f3; PF(f3); ST(2, 1, 0, o);
    }

    // ---- tail (rem <= 7 plain steps; drift bounded, fp32-safe) ----
    {
        float o;
        if (rem > 0) { o = f0; PF(f0); ST(0, 0, 1, o); }
        if (rem > 1) { o = f1; PF(f1); ST(0, 1, 0, o); }
        if (rem > 2) { o = f2; PF(f2); ST(0, 0, 1, o); }
        if (rem > 3) { o = f3;         ST(0, 1, 0, o); }
        if (rem > 4) { o = f0;         ST(0, 0, 1, o); }
        if (rem > 5) { o = f1;         ST(0, 1, 0, o); }
        if (rem > 6) { o = f2;         ST(0, 0, 1, o); }
    }
#undef PF
#undef ST

    if (dir == 0) {
        // One extra plain matvec (obs contribution 0 -> eo = 1): u = T^T alpha_mid.
        // Current data sits in psh[0] if nsteps even, else psh[1].
        if (nsteps & 1)
            pn = crf_step<0>(tc, psh[1], psh[0], 0.0f, C, wred, warp, lane, j);
        else
            pn = crf_step<0>(tc, psh[0], psh[1], 0.0f, C, wred, warp, lane, j);
        g_u[b * NSTATES + j] = pn;
        if (j == 0) g_Cf[b] = C;
    } else {
        g_d[b * NSTATES + j] = pn;
        if (j == 0) g_Cb[b] = C;
    }
}

// Combine: out[b] = -(Cf + Cb + log(sum_j u[j] * delta[j]))
__global__ void __launch_bounds__(128, 1)
crf_combine_kernel(float* __restrict__ out)
{
    const int b    = blockIdx.x;
    const int j    = threadIdx.x;
    const int warp = j >> 5;
    const int lane = j & 31;
    __shared__ float wred[4];

    float v = g_u[b * NSTATES + j] * g_d[b * NSTATES + j];
    float s = warp_sum(v);
    if (lane == 0) wred[warp] = s;
    __syncthreads();
    if (j == 0) {
        float tot = (wred[0] + wred[1]) + (wred[2] + wred[3]);
        out[b] = -(g_Cf[b] + g_Cb[b] + logf(tot));
    }
}

extern "C" void kernel_launch(void* const* d_in, const int* in_sizes, int n_in,
                              void* d_out, int out_size)
{
    const float* obs  = (const float*)d_in[0];   // [B, T, S] fp32
    const float* logA = (const float*)d_in[1];   // [S, S] fp32
    float* out = (float*)d_out;                  // [B] fp32

    const int B = out_size;                      // 64
    const int T = in_sizes[0] / (B * NSTATES);   // 4096

    crf_half_kernel<<<2 * B, NSTATES>>>(obs, logA, T);
    crf_combine_kernel<<<B, NSTATES>>>(out);
}